// round 8
// baseline (speedup 1.0000x reference)
#include <cuda_runtime.h>
#include <cuda_fp16.h>
#include <math.h>

#define L_SEQ 2048
#define H_DIM 2048
#define G3H   6144
#define NCTA  128
#define TPB   512     // 16 warps; warp w owns j = cta*16 + w
#define FLAG_STRIDE 8 // words between per-CTA flags (32B spacing)

// -------- device-global scratch (no allocations allowed) --------
__device__ float g_gi[(size_t)L_SEQ * G3H];         // 48 MB: x@W_ih^T + b_ih (+ b_hh for r,z)
__device__ __align__(16) __half g_h16[2][H_DIM];    // double-buffered fp16 h broadcast
__device__ unsigned int g_hflag[NCTA * FLAG_STRIDE];// per-CTA progress flags (step count)

__device__ __forceinline__ __half2 u2h2(unsigned u) {
    return *reinterpret_cast<__half2*>(&u);
}

// fast sigmoid / tanh via MUFU (ex2 + rcp), rel err ~1e-6
__device__ __forceinline__ float fsig(float x) {
    float e, r;
    asm("ex2.approx.ftz.f32 %0, %1;" : "=f"(e) : "f"(-1.4426950408889634f * x));
    asm("rcp.approx.ftz.f32 %0, %1;" : "=f"(r) : "f"(1.0f + e));
    return r;
}
__device__ __forceinline__ float ftanh(float x) {
    float e, r;
    asm("ex2.approx.ftz.f32 %0, %1;" : "=f"(e) : "f"(2.8853900817779268f * x));  // e^(2x)
    asm("rcp.approx.ftz.f32 %0, %1;" : "=f"(r) : "f"(1.0f + e));
    return 1.0f - 2.0f * r;
}

// ============================================================
// Kernel A (reverted to the R4/R6-proven 64x64 tile):
// g_gi[t][r] = x[t]·w_ih[r] + b_ih[r] + (r<2H ? b_hh[r] : 0)
// (n-gate's b_hh must stay inside the reset product — added in kernel B)
// Block (0,0) also zeroes the per-CTA flags for this launch.
// ============================================================
#define BM 64
#define BN 64
#define BK 16

__global__ void __launch_bounds__(256) gemm_gi_kernel(const float* __restrict__ X,
                                                      const float* __restrict__ W,
                                                      const float* __restrict__ b_ih,
                                                      const float* __restrict__ b_hh) {
    if (blockIdx.x == 0 && blockIdx.y == 0) {
#pragma unroll
        for (int i = 0; i < 4; i++)
            g_hflag[threadIdx.x + i * 256] = 0u;    // 1024 words
    }

    __shared__ float As[BK][BM + 4];
    __shared__ float Bs[BK][BN + 4];
    const int K = H_DIM;
    const int bm = blockIdx.y * BM;
    const int bn = blockIdx.x * BN;
    const int tid = threadIdx.x;
    const int tm = tid >> 4;
    const int tn = tid & 15;

    unsigned long long c[2][4];
#pragma unroll
    for (int i = 0; i < 2; i++)
#pragma unroll
        for (int j = 0; j < 4; j++) c[i][j] = 0ull;

    const int lrow = tid >> 2;
    const int lk   = (tid & 3) << 2;

    for (int k0 = 0; k0 < K; k0 += BK) {
        float4 av = *reinterpret_cast<const float4*>(&X[(size_t)(bm + lrow) * K + k0 + lk]);
        float4 bv = *reinterpret_cast<const float4*>(&W[(size_t)(bn + lrow) * K + k0 + lk]);
        As[lk + 0][lrow] = av.x; As[lk + 1][lrow] = av.y;
        As[lk + 2][lrow] = av.z; As[lk + 3][lrow] = av.w;
        Bs[lk + 0][lrow] = bv.x; Bs[lk + 1][lrow] = bv.y;
        Bs[lk + 2][lrow] = bv.z; Bs[lk + 3][lrow] = bv.w;
        __syncthreads();
#pragma unroll
        for (int k = 0; k < BK; k++) {
            float4 a = *reinterpret_cast<const float4*>(&As[k][tm << 2]);
            float4 b = *reinterpret_cast<const float4*>(&Bs[k][tn << 2]);
            unsigned long long a01, a23;
            asm("mov.b64 %0, {%1, %2};" : "=l"(a01) : "r"(__float_as_uint(a.x)), "r"(__float_as_uint(a.y)));
            asm("mov.b64 %0, {%1, %2};" : "=l"(a23) : "r"(__float_as_uint(a.z)), "r"(__float_as_uint(a.w)));
            float bj[4] = {b.x, b.y, b.z, b.w};
#pragma unroll
            for (int j = 0; j < 4; j++) {
                unsigned long long bb;
                asm("mov.b64 %0, {%1, %1};" : "=l"(bb) : "r"(__float_as_uint(bj[j])));
                asm("fma.rn.f32x2 %0, %1, %2, %0;" : "+l"(c[0][j]) : "l"(a01), "l"(bb));
                asm("fma.rn.f32x2 %0, %1, %2, %0;" : "+l"(c[1][j]) : "l"(a23), "l"(bb));
            }
        }
        __syncthreads();
    }
#pragma unroll
    for (int i2 = 0; i2 < 2; i2++) {
#pragma unroll
        for (int j = 0; j < 4; j++) {
            unsigned lo, hi;
            asm("mov.b64 {%0, %1}, %2;" : "=r"(lo), "=r"(hi) : "l"(c[i2][j]));
            int col  = bn + (tn << 2) + j;
            float bs = b_ih[col] + ((col < 2 * H_DIM) ? b_hh[col] : 0.0f);
            int row0 = bm + (tm << 2) + i2 * 2;
            g_gi[(size_t)row0 * G3H + col]       = __uint_as_float(lo) + bs;
            g_gi[(size_t)(row0 + 1) * G3H + col] = __uint_as_float(hi) + bs;
        }
    }
}

// ============================================================
// Kernel B: persistent GRU recurrence (R7 form, unchanged).
// 128 CTAs x 512 threads (16 warps). Warp w owns j = cta*16 + w:
// 3 gate rows, weights in 96 half2 registers per lane.
// Per step: lane0 gi prefetch -> consumers (tid<256) poll per-CTA
// flag + fetch own uint4 of h -> bar -> reg matvec (32-MAC fp16
// chains) -> butterfly reduce -> lane0 fast gates -> h to SMEM ->
// bar -> tid0 vectorized publish (2x STG.128.cg + release flag) ->
// lane0 out store (off critical path).
// ============================================================
__global__ void __launch_bounds__(TPB, 1) gru_kernel(const float* __restrict__ w_hh,
                                                     const float* __restrict__ b_hh,
                                                     float* __restrict__ out,
                                                     int out_elems) {
    __shared__ uint4 sH[H_DIM / 8];                       // 4KB h_t
    __shared__ __align__(16) unsigned short sNewH[16];    // this CTA's new h (fp16)

    const int tid  = threadIdx.x;
    const int warp = tid >> 5;
    const int lane = tid & 31;
    const int cta  = blockIdx.x;
    const int j    = cta * 16 + warp;

    // ---- prologue: 3 rows of W_hh into 96 half2 registers ----
    __half2 w[3][8][4];
#pragma unroll
    for (int g = 0; g < 3; g++) {
        const float* wr = w_hh + (size_t)(g * H_DIM + j) * H_DIM;
#pragma unroll
        for (int i = 0; i < 8; i++) {
            int k = i * 256 + lane * 8;
            float4 a = *reinterpret_cast<const float4*>(wr + k);
            float4 b = *reinterpret_cast<const float4*>(wr + k + 4);
            w[g][i][0] = __floats2half2_rn(a.x, a.y);
            w[g][i][1] = __floats2half2_rn(a.z, a.w);
            w[g][i][2] = __floats2half2_rn(b.x, b.y);
            w[g][i][3] = __floats2half2_rn(b.z, b.w);
        }
    }

    float h_own = 0.0f;
    const float bhn = (lane == 0) ? b_hh[2 * H_DIM + j] : 0.0f;
    const float* gi_ptr  = g_gi + j;
    float*       out_ptr = out + j;
    const unsigned int* my_flag = &g_hflag[(tid >> 1) * FLAG_STRIDE];

    // ================= step 0 (h = 0, no poll) =================
    if (lane == 0) {
        float ir  = gi_ptr[0];
        float iz  = gi_ptr[H_DIM];
        float inn = gi_ptr[2 * H_DIM];
        float rg = fsig(ir);
        float zg = fsig(iz);
        float ng = ftanh(inn + rg * bhn);
        h_own = (1.0f - zg) * ng;
        sNewH[warp] = (unsigned short)__half_as_ushort(__float2half(h_own));
    }
    __syncthreads();
    if (tid == 0) {
        uint4 lo = *reinterpret_cast<const uint4*>(&sNewH[0]);
        uint4 hi = *reinterpret_cast<const uint4*>(&sNewH[8]);
        __half* dst = &g_h16[1][cta * 16];
        asm volatile("st.global.cg.v4.u32 [%0], {%1,%2,%3,%4};"
                     :: "l"(dst), "r"(lo.x), "r"(lo.y), "r"(lo.z), "r"(lo.w) : "memory");
        asm volatile("st.global.cg.v4.u32 [%0], {%1,%2,%3,%4};"
                     :: "l"(dst + 8), "r"(hi.x), "r"(hi.y), "r"(hi.z), "r"(hi.w) : "memory");
        asm volatile("st.release.gpu.global.u32 [%0], %1;"
                     :: "l"(&g_hflag[cta * FLAG_STRIDE]), "r"(1u) : "memory");
    }
    if (lane == 0) out_ptr[0] = h_own;
    gi_ptr  += G3H;
    out_ptr += H_DIM;

    // ================= steps 1..L-1 =================
    for (int t = 1; t < L_SEQ; t++) {
        // ---- gi prefetch (lands while polling) ----
        float ir = 0.f, iz = 0.f, inn = 0.f;
        if (lane == 0) {
            ir  = gi_ptr[0];
            iz  = gi_ptr[H_DIM];
            inn = gi_ptr[2 * H_DIM];
        }

        // ---- fused wait + fetch ----
        if (tid < H_DIM / 8) {
            const unsigned tg = (unsigned)t;
            unsigned v;
            do {
                asm volatile("ld.acquire.gpu.global.u32 %0, [%1];"
                             : "=r"(v) : "l"(my_flag) : "memory");
            } while (v < tg);
            sH[tid] = __ldcg(reinterpret_cast<const uint4*>(&g_h16[t & 1][0]) + tid);
        }
        __syncthreads();

        // ---- matvec: 3 rows, 32-MAC fp16 chains, flush to fp32 ----
        float acc[3] = {0.f, 0.f, 0.f};
#pragma unroll
        for (int ii = 0; ii < 2; ii++) {
            const int base = ii * 4;
            uint4 p = sH[(base + 0) * 32 + lane];
            uint4 q = sH[(base + 1) * 32 + lane];
            __half2 s[3];
#pragma unroll
            for (int g = 0; g < 3; g++) {
                __half2 t0 = __hmul2(w[g][base + 0][0], u2h2(p.x));
                t0 = __hfma2(w[g][base + 0][1], u2h2(p.y), t0);
                t0 = __hfma2(w[g][base + 0][2], u2h2(p.z), t0);
                t0 = __hfma2(w[g][base + 0][3], u2h2(p.w), t0);
                t0 = __hfma2(w[g][base + 1][0], u2h2(q.x), t0);
                t0 = __hfma2(w[g][base + 1][1], u2h2(q.y), t0);
                t0 = __hfma2(w[g][base + 1][2], u2h2(q.z), t0);
                t0 = __hfma2(w[g][base + 1][3], u2h2(q.w), t0);
                s[g] = t0;
            }
            p = sH[(base + 2) * 32 + lane];
            q = sH[(base + 3) * 32 + lane];
#pragma unroll
            for (int g = 0; g < 3; g++) {
                __half2 t0 = s[g];
                t0 = __hfma2(w[g][base + 2][0], u2h2(p.x), t0);
                t0 = __hfma2(w[g][base + 2][1], u2h2(p.y), t0);
                t0 = __hfma2(w[g][base + 2][2], u2h2(p.z), t0);
                t0 = __hfma2(w[g][base + 2][3], u2h2(p.w), t0);
                t0 = __hfma2(w[g][base + 3][0], u2h2(q.x), t0);
                t0 = __hfma2(w[g][base + 3][1], u2h2(q.y), t0);
                t0 = __hfma2(w[g][base + 3][2], u2h2(q.z), t0);
                t0 = __hfma2(w[g][base + 3][3], u2h2(q.w), t0);
                float2 f = __half22float2(t0);
                acc[g] += f.x + f.y;
            }
        }

        // ---- butterfly reduce over 32 lanes ----
#pragma unroll
        for (int off = 16; off; off >>= 1) {
#pragma unroll
            for (int g = 0; g < 3; g++)
                acc[g] += __shfl_xor_sync(0xffffffffu, acc[g], off);
        }

        // ---- gates (lane 0, fast MUFU path) ----
        if (lane == 0) {
            float rg = fsig(ir + acc[0]);
            float zg = fsig(iz + acc[1]);
            float ng = ftanh(inn + rg * (acc[2] + bhn));
            float hn = (1.0f - zg) * ng + zg * h_own;
            h_own = hn;
            sNewH[warp] = (unsigned short)__half_as_ushort(__float2half(hn));
        }
        __syncthreads();

        // ---- vectorized publish: 32B h store + release flag (tid0) ----
        if (tid == 0) {
            uint4 lo = *reinterpret_cast<const uint4*>(&sNewH[0]);
            uint4 hi = *reinterpret_cast<const uint4*>(&sNewH[8]);
            __half* dst = &g_h16[(t + 1) & 1][cta * 16];
            asm volatile("st.global.cg.v4.u32 [%0], {%1,%2,%3,%4};"
                         :: "l"(dst), "r"(lo.x), "r"(lo.y), "r"(lo.z), "r"(lo.w) : "memory");
            asm volatile("st.global.cg.v4.u32 [%0], {%1,%2,%3,%4};"
                         :: "l"(dst + 8), "r"(hi.x), "r"(hi.y), "r"(hi.z), "r"(hi.w) : "memory");
            asm volatile("st.release.gpu.global.u32 [%0], %1;"
                         :: "l"(&g_hflag[cta * FLAG_STRIDE]), "r"((unsigned)(t + 1)) : "memory");
        }
        // ---- out store: after bar, off the release drain ----
        if (lane == 0) out_ptr[0] = h_own;

        gi_ptr  += G3H;
        out_ptr += H_DIM;
    }

    // ---- final hidden state (both tails of d_out) ----
    if (lane == 0) {
        size_t base = (size_t)L_SEQ * H_DIM;
        if ((long long)(base + j) < (long long)out_elems)          out[base + j] = h_own;
        if ((long long)(base + H_DIM + j) < (long long)out_elems)  out[base + H_DIM + j] = h_own;
    }
}

// ============================================================
extern "C" void kernel_launch(void* const* d_in, const int* in_sizes, int n_in,
                              void* d_out, int out_size) {
    const float* x    = (const float*)d_in[0];
    const float* w_ih = (const float*)d_in[1];
    const float* w_hh = (const float*)d_in[2];
    const float* b_ih = (const float*)d_in[3];
    const float* b_hh = (const float*)d_in[4];
    float* out = (float*)d_out;

    gemm_gi_kernel<<<dim3(G3H / BN, L_SEQ / BM), 256>>>(x, w_ih, b_ih, b_hh);
    gru_kernel<<<NCTA, TPB>>>(w_hh, b_hh, out, out_size);
}

// round 9
// speedup vs baseline: 1.1162x; 1.1162x over previous
#include <cuda_runtime.h>
#include <cuda_fp16.h>
#include <math.h>

#define L_SEQ 2048
#define H_DIM 2048
#define G3H   6144
#define NCTA  128
#define TPB   512     // 16 warps; warp w owns j = cta*16 + w

// -------- device-global scratch (no allocations allowed) --------
__device__ float g_gi[(size_t)L_SEQ * G3H];        // 48 MB: x@W_ih^T + b_ih (+ b_hh for r,z)
__device__ __align__(16) __half g_h16[2][H_DIM];   // double-buffered fp16 h
__device__ unsigned int g_sync;                    // monotonic arrival counter

__device__ __forceinline__ __half2 u2h2(unsigned u) {
    return *reinterpret_cast<__half2*>(&u);
}

// fast sigmoid / tanh via MUFU (ex2 + rcp), rel err ~1e-6
__device__ __forceinline__ float fsig(float x) {
    float e, r;
    asm("ex2.approx.ftz.f32 %0, %1;" : "=f"(e) : "f"(-1.4426950408889634f * x));
    asm("rcp.approx.ftz.f32 %0, %1;" : "=f"(r) : "f"(1.0f + e));
    return r;
}
__device__ __forceinline__ float ftanh(float x) {
    float e, r;
    asm("ex2.approx.ftz.f32 %0, %1;" : "=f"(e) : "f"(2.8853900817779268f * x));  // e^(2x)
    asm("rcp.approx.ftz.f32 %0, %1;" : "=f"(r) : "f"(1.0f + e));
    return 1.0f - 2.0f * r;
}

// ============================================================
// Kernel A: g_gi[t][r] = x[t]·w_ih[r] + b_ih[r] + (r<2H ? b_hh[r] : 0)
// b_hh folds into the sigmoid gates only; the n-gate's b_hh must stay
// inside the reset-gate product: n = tanh(i_n + r*(h·W_n + b_hh_n)).
// ============================================================
#define BM 64
#define BN 64
#define BK 16

__global__ void __launch_bounds__(256) gemm_gi_kernel(const float* __restrict__ X,
                                                      const float* __restrict__ W,
                                                      const float* __restrict__ b_ih,
                                                      const float* __restrict__ b_hh) {
    if (blockIdx.x == 0 && blockIdx.y == 0 && threadIdx.x == 0) g_sync = 0u;

    __shared__ float As[BK][BM + 4];
    __shared__ float Bs[BK][BN + 4];
    const int K = H_DIM;
    const int bm = blockIdx.y * BM;
    const int bn = blockIdx.x * BN;
    const int tid = threadIdx.x;
    const int tm = tid >> 4;
    const int tn = tid & 15;

    unsigned long long c[2][4];
#pragma unroll
    for (int i = 0; i < 2; i++)
#pragma unroll
        for (int j = 0; j < 4; j++) c[i][j] = 0ull;

    const int lrow = tid >> 2;
    const int lk   = (tid & 3) << 2;

    for (int k0 = 0; k0 < K; k0 += BK) {
        float4 av = *reinterpret_cast<const float4*>(&X[(size_t)(bm + lrow) * K + k0 + lk]);
        float4 bv = *reinterpret_cast<const float4*>(&W[(size_t)(bn + lrow) * K + k0 + lk]);
        As[lk + 0][lrow] = av.x; As[lk + 1][lrow] = av.y;
        As[lk + 2][lrow] = av.z; As[lk + 3][lrow] = av.w;
        Bs[lk + 0][lrow] = bv.x; Bs[lk + 1][lrow] = bv.y;
        Bs[lk + 2][lrow] = bv.z; Bs[lk + 3][lrow] = bv.w;
        __syncthreads();
#pragma unroll
        for (int k = 0; k < BK; k++) {
            float4 a = *reinterpret_cast<const float4*>(&As[k][tm << 2]);
            float4 b = *reinterpret_cast<const float4*>(&Bs[k][tn << 2]);
            unsigned long long a01, a23;
            asm("mov.b64 %0, {%1, %2};" : "=l"(a01) : "r"(__float_as_uint(a.x)), "r"(__float_as_uint(a.y)));
            asm("mov.b64 %0, {%1, %2};" : "=l"(a23) : "r"(__float_as_uint(a.z)), "r"(__float_as_uint(a.w)));
            float bj[4] = {b.x, b.y, b.z, b.w};
#pragma unroll
            for (int j = 0; j < 4; j++) {
                unsigned long long bb;
                asm("mov.b64 %0, {%1, %1};" : "=l"(bb) : "r"(__float_as_uint(bj[j])));
                asm("fma.rn.f32x2 %0, %1, %2, %0;" : "+l"(c[0][j]) : "l"(a01), "l"(bb));
                asm("fma.rn.f32x2 %0, %1, %2, %0;" : "+l"(c[1][j]) : "l"(a23), "l"(bb));
            }
        }
        __syncthreads();
    }
#pragma unroll
    for (int i2 = 0; i2 < 2; i2++) {
#pragma unroll
        for (int j = 0; j < 4; j++) {
            unsigned lo, hi;
            asm("mov.b64 {%0, %1}, %2;" : "=r"(lo), "=r"(hi) : "l"(c[i2][j]));
            int col  = bn + (tn << 2) + j;
            float bs = b_ih[col] + ((col < 2 * H_DIM) ? b_hh[col] : 0.0f);
            int row0 = bm + (tm << 2) + i2 * 2;
            g_gi[(size_t)row0 * G3H + col]       = __uint_as_float(lo) + bs;
            g_gi[(size_t)(row0 + 1) * G3H + col] = __uint_as_float(hi) + bs;
        }
    }
}

// ============================================================
// Kernel B: persistent GRU recurrence (exact R4 structure; only the
// activation functions swapped to MUFU fast paths).
// 128 CTAs x 512 threads (16 warps). Warp w owns j = cta*16 + w:
// 3 gate rows, weights in 96 half2 registers per lane.
// Per step: gi prefetch -> tid0 polls counter -> bar -> stage h to
// SMEM (4KB) -> bar -> reg matvec -> butterfly reduce -> lane0
// gates -> store h -> bar -> red.release arrive.
// ============================================================
__global__ void __launch_bounds__(TPB, 1) gru_kernel(const float* __restrict__ w_hh,
                                                     const float* __restrict__ b_hh,
                                                     float* __restrict__ out,
                                                     int out_elems) {
    __shared__ uint4 sH[H_DIM / 8];     // 2048 halfs = 4KB

    const int tid  = threadIdx.x;
    const int warp = tid >> 5;
    const int lane = tid & 31;
    const int j    = blockIdx.x * 16 + warp;

    // ---- prologue: 3 rows of W_hh into 96 half2 registers ----
    __half2 w[3][8][4];
#pragma unroll
    for (int g = 0; g < 3; g++) {
        const float* wr = w_hh + (size_t)(g * H_DIM + j) * H_DIM;
#pragma unroll
        for (int i = 0; i < 8; i++) {
            int k = i * 256 + lane * 8;
            float4 a = *reinterpret_cast<const float4*>(wr + k);
            float4 b = *reinterpret_cast<const float4*>(wr + k + 4);
            w[g][i][0] = __floats2half2_rn(a.x, a.y);
            w[g][i][1] = __floats2half2_rn(a.z, a.w);
            w[g][i][2] = __floats2half2_rn(b.x, b.y);
            w[g][i][3] = __floats2half2_rn(b.z, b.w);
        }
    }

    float h_own = 0.0f;
    const float bhn = (lane == 0) ? b_hh[2 * H_DIM + j] : 0.0f;  // n-gate recurrent bias
    const float* gi_ptr  = g_gi + j;
    float*       out_ptr = out + j;

    for (int t = 0; t < L_SEQ; t++) {
        // ---- gi prefetch (lands while polling) ----
        float ir = 0.f, iz = 0.f, inn = 0.f;
        if (lane == 0) {
            ir  = gi_ptr[0];
            iz  = gi_ptr[H_DIM];
            inn = gi_ptr[2 * H_DIM];
        }

        if (t > 0) {
            // ---- chip-wide wait for step t's h ----
            if (tid == 0) {
                unsigned target = (unsigned)t << 7;    // t * NCTA
                unsigned v;
                do {
                    asm volatile("ld.acquire.gpu.global.u32 %0, [%1];"
                                 : "=r"(v) : "l"(&g_sync) : "memory");
                } while (v < target);
            }
            __syncthreads();
            // ---- stage h into SMEM: 256 lanes x uint4 = 4KB ----
            if (tid < H_DIM / 8)
                sH[tid] = __ldcg(reinterpret_cast<const uint4*>(&g_h16[t & 1][0]) + tid);
            __syncthreads();
        }

        // ---- matvec: 3 rows, weights in regs, h from SMEM ----
        float acc[3] = {0.f, 0.f, 0.f};
        if (t > 0) {
#pragma unroll
            for (int ii = 0; ii < 4; ii++) {
                uint4 hv0 = sH[(2 * ii) * 32 + lane];
                uint4 hv1 = sH[(2 * ii + 1) * 32 + lane];
                __half2 a0 = u2h2(hv0.x), a1 = u2h2(hv0.y), a2 = u2h2(hv0.z), a3 = u2h2(hv0.w);
                __half2 b0 = u2h2(hv1.x), b1 = u2h2(hv1.y), b2 = u2h2(hv1.z), b3 = u2h2(hv1.w);
#pragma unroll
                for (int g = 0; g < 3; g++) {
                    __half2 s = __hmul2(w[g][2 * ii][0], a0);
                    s = __hfma2(w[g][2 * ii][1], a1, s);
                    s = __hfma2(w[g][2 * ii][2], a2, s);
                    s = __hfma2(w[g][2 * ii][3], a3, s);
                    s = __hfma2(w[g][2 * ii + 1][0], b0, s);
                    s = __hfma2(w[g][2 * ii + 1][1], b1, s);
                    s = __hfma2(w[g][2 * ii + 1][2], b2, s);
                    s = __hfma2(w[g][2 * ii + 1][3], b3, s);
                    float2 f = __half22float2(s);     // flush to fp32 every 16 MACs
                    acc[g] += f.x + f.y;
                }
            }
        }

        // ---- butterfly reduce over 32 lanes ----
#pragma unroll
        for (int off = 16; off; off >>= 1) {
#pragma unroll
            for (int g = 0; g < 3; g++)
                acc[g] += __shfl_xor_sync(0xffffffffu, acc[g], off);
        }

        // ---- gates + state update (lane 0, MUFU fast path) ----
        if (lane == 0) {
            float rg = fsig(ir + acc[0]);
            float zg = fsig(iz + acc[1]);
            float ng = ftanh(inn + rg * (acc[2] + bhn));
            float hn = (1.0f - zg) * ng + zg * h_own;
            h_own = hn;
            out_ptr[0] = hn;
            g_h16[(t + 1) & 1][j] = __float2half(hn);
            if (t == L_SEQ - 1) {
                size_t base = (size_t)L_SEQ * H_DIM;
                if ((long long)(base + j) < out_elems)          out[base + j] = hn;
                if ((long long)(base + H_DIM + j) < out_elems)  out[base + H_DIM + j] = hn;
            }
        }
        __syncthreads();   // all h stores done; also guards sH reuse

        // ---- arrive ----
        if (tid == 0) {
            asm volatile("red.release.gpu.global.add.u32 [%0], %1;"
                         :: "l"(&g_sync), "r"(1u) : "memory");
        }

        gi_ptr  += G3H;
        out_ptr += H_DIM;
    }
}

// ============================================================
extern "C" void kernel_launch(void* const* d_in, const int* in_sizes, int n_in,
                              void* d_out, int out_size) {
    const float* x    = (const float*)d_in[0];
    const float* w_ih = (const float*)d_in[1];
    const float* w_hh = (const float*)d_in[2];
    const float* b_ih = (const float*)d_in[3];
    const float* b_hh = (const float*)d_in[4];
    float* out = (float*)d_out;

    gemm_gi_kernel<<<dim3(G3H / BN, L_SEQ / BM), 256>>>(x, w_ih, b_ih, b_hh);
    gru_kernel<<<NCTA, TPB>>>(w_hh, b_hh, out, out_size);
}

// round 12
// speedup vs baseline: 1.3734x; 1.2305x over previous
#include <cuda_runtime.h>
#include <cuda_fp16.h>
#include <mma.h>
#include <math.h>

using namespace nvcuda;

#define L_SEQ 2048
#define H_DIM 2048
#define G3H   6144
#define NCTA  128
#define TPB   512     // 16 warps; warp w owns j = cta*16 + w

// -------- device-global scratch (no allocations allowed) --------
__device__ float g_gi[(size_t)L_SEQ * G3H];        // 48 MB: raw x@W_ih^T (bias added in kernel B)
__device__ __align__(16) __half g_h16[2][H_DIM];   // double-buffered fp16 h
__device__ unsigned int g_sync;                    // monotonic arrival counter
__device__ __align__(16) __half g_x16[(size_t)L_SEQ * H_DIM];   // 8 MB fp16 x
__device__ __align__(16) __half g_w16[(size_t)G3H * H_DIM];     // 24 MB fp16 w_ih

__device__ __forceinline__ __half2 u2h2(unsigned u) {
    return *reinterpret_cast<__half2*>(&u);
}

// fast sigmoid / tanh via MUFU (ex2 + rcp), rel err ~1e-6
__device__ __forceinline__ float fsig(float x) {
    float e, r;
    asm("ex2.approx.ftz.f32 %0, %1;" : "=f"(e) : "f"(-1.4426950408889634f * x));
    asm("rcp.approx.ftz.f32 %0, %1;" : "=f"(r) : "f"(1.0f + e));
    return r;
}
__device__ __forceinline__ float ftanh(float x) {
    float e, r;
    asm("ex2.approx.ftz.f32 %0, %1;" : "=f"(e) : "f"(2.8853900817779268f * x));  // e^(2x)
    asm("rcp.approx.ftz.f32 %0, %1;" : "=f"(r) : "f"(1.0f + e));
    return 1.0f - 2.0f * r;
}

// ============================================================
// fp32 -> fp16 conversion. Device globals referenced from DEVICE
// code only (passing __device__ arrays as host-side kernel args
// passes the host shadow symbol — the R10/R11 bug).
// ============================================================
__device__ __forceinline__ void cvt_body(const float* __restrict__ src,
                                         __half* __restrict__ dst, int i) {
    float4 f0 = reinterpret_cast<const float4*>(src)[2 * i];
    float4 f1 = reinterpret_cast<const float4*>(src)[2 * i + 1];
    __half2 h0 = __floats2half2_rn(f0.x, f0.y);
    __half2 h1 = __floats2half2_rn(f0.z, f0.w);
    __half2 h2 = __floats2half2_rn(f1.x, f1.y);
    __half2 h3 = __floats2half2_rn(f1.z, f1.w);
    uint4 v;
    v.x = *reinterpret_cast<unsigned*>(&h0);
    v.y = *reinterpret_cast<unsigned*>(&h1);
    v.z = *reinterpret_cast<unsigned*>(&h2);
    v.w = *reinterpret_cast<unsigned*>(&h3);
    reinterpret_cast<uint4*>(dst)[i] = v;
}

__global__ void cvt_x_kernel(const float* __restrict__ src) {
    int i = blockIdx.x * blockDim.x + threadIdx.x;
    if (i == 0) g_sync = 0u;
    if (i < L_SEQ * H_DIM / 8) cvt_body(src, g_x16, i);
}

__global__ void cvt_w_kernel(const float* __restrict__ src) {
    int i = blockIdx.x * blockDim.x + threadIdx.x;
    if (i < G3H * H_DIM / 8) cvt_body(src, g_w16, i);
}

// ============================================================
// Kernel A: tensor-core GEMM via wmma (compiler-owned layouts).
// g_gi[t][c] = sum_k x16[t][k] * w16[c][k]   (raw product, no bias)
// Tile 128(M) x 64(N) x 32(K); 8 warps (4m x 2n); warp tile 32x32 =
// 2x2 wmma 16x16x16 fragments, fp32 accumulators.
// ============================================================
#define GM 128
#define GN 64
#define GK 32
#define GP (GK + 8)   // SMEM pitch in halfs

__global__ void __launch_bounds__(256) gemm_gi_kernel() {
    __shared__ __half Asm[GM][GP];
    __shared__ __half Bsm[GN][GP];

    const int bm = blockIdx.y * GM;      // time rows
    const int bn = blockIdx.x * GN;      // gate cols
    const int tid  = threadIdx.x;
    const int warp = tid >> 5;
    const int wm = warp >> 1;            // 0..3
    const int wn = warp & 1;             // 0..1

    wmma::fragment<wmma::accumulator, 16, 16, 16, float> fc[2][2];
#pragma unroll
    for (int i = 0; i < 2; i++)
#pragma unroll
        for (int jn = 0; jn < 2; jn++)
            wmma::fill_fragment(fc[i][jn], 0.0f);

    // G->S load coords
    const int arow = tid >> 1, acolh = (tid & 1) * 16;   // A: 128 rows x 32 halfs
    const int brow = tid >> 2, bcolh = (tid & 3) * 8;    // B: 64 rows x 32 halfs

    for (int k0 = 0; k0 < H_DIM; k0 += GK) {
        {
            const uint4* asrc = reinterpret_cast<const uint4*>(
                &g_x16[(size_t)(bm + arow) * H_DIM + k0 + acolh]);
            uint4 av0 = asrc[0], av1 = asrc[1];
            *reinterpret_cast<uint4*>(&Asm[arow][acolh])     = av0;
            *reinterpret_cast<uint4*>(&Asm[arow][acolh + 8]) = av1;
            uint4 bv = *reinterpret_cast<const uint4*>(
                &g_w16[(size_t)(bn + brow) * H_DIM + k0 + bcolh]);
            *reinterpret_cast<uint4*>(&Bsm[brow][bcolh]) = bv;
        }
        __syncthreads();

#pragma unroll
        for (int kk = 0; kk < GK; kk += 16) {
            wmma::fragment<wmma::matrix_a, 16, 16, 16, __half, wmma::row_major> fa[2];
            wmma::fragment<wmma::matrix_b, 16, 16, 16, __half, wmma::col_major> fb[2];
#pragma unroll
            for (int i = 0; i < 2; i++)
                wmma::load_matrix_sync(fa[i], &Asm[wm * 32 + i * 16][kk], GP);
#pragma unroll
            for (int jn = 0; jn < 2; jn++)
                wmma::load_matrix_sync(fb[jn], &Bsm[wn * 32 + jn * 16][kk], GP);
#pragma unroll
            for (int i = 0; i < 2; i++)
#pragma unroll
                for (int jn = 0; jn < 2; jn++)
                    wmma::mma_sync(fc[i][jn], fa[i], fb[jn], fc[i][jn]);
        }
        __syncthreads();
    }

    // writeback (raw product; biases added in the recurrence kernel)
#pragma unroll
    for (int i = 0; i < 2; i++)
#pragma unroll
        for (int jn = 0; jn < 2; jn++) {
            int row = bm + wm * 32 + i * 16;
            int col = bn + wn * 32 + jn * 16;
            wmma::store_matrix_sync(&g_gi[(size_t)row * G3H + col], fc[i][jn],
                                    G3H, wmma::mem_row_major);
        }
}

// ============================================================
// Kernel B: persistent GRU recurrence (R9 structure; biases applied
// here since the GEMM writes the raw product).
// 128 CTAs x 512 threads (16 warps). Warp w owns j = cta*16 + w.
// ============================================================
__global__ void __launch_bounds__(TPB, 1) gru_kernel(const float* __restrict__ w_hh,
                                                     const float* __restrict__ b_ih,
                                                     const float* __restrict__ b_hh,
                                                     float* __restrict__ out,
                                                     int out_elems) {
    __shared__ uint4 sH[H_DIM / 8];     // 2048 halfs = 4KB

    const int tid  = threadIdx.x;
    const int warp = tid >> 5;
    const int lane = tid & 31;
    const int j    = blockIdx.x * 16 + warp;

    // ---- prologue: 3 rows of W_hh into 96 half2 registers ----
    __half2 w[3][8][4];
#pragma unroll
    for (int g = 0; g < 3; g++) {
        const float* wr = w_hh + (size_t)(g * H_DIM + j) * H_DIM;
#pragma unroll
        for (int i = 0; i < 8; i++) {
            int k = i * 256 + lane * 8;
            float4 a = *reinterpret_cast<const float4*>(wr + k);
            float4 b = *reinterpret_cast<const float4*>(wr + k + 4);
            w[g][i][0] = __floats2half2_rn(a.x, a.y);
            w[g][i][1] = __floats2half2_rn(a.z, a.w);
            w[g][i][2] = __floats2half2_rn(b.x, b.y);
            w[g][i][3] = __floats2half2_rn(b.z, b.w);
        }
    }

    float h_own = 0.0f;
    // lane-0 bias registers: r,z get b_ih+b_hh; n gets b_ih only,
    // with b_hh_n kept inside the reset-gate product (torch semantics).
    float bir = 0.f, biz = 0.f, bin = 0.f, bhn = 0.f;
    if (lane == 0) {
        bir = b_ih[j]             + b_hh[j];
        biz = b_ih[H_DIM + j]     + b_hh[H_DIM + j];
        bin = b_ih[2 * H_DIM + j];
        bhn = b_hh[2 * H_DIM + j];
    }
    const float* gi_ptr  = g_gi + j;
    float*       out_ptr = out + j;

    for (int t = 0; t < L_SEQ; t++) {
        // ---- gi prefetch (lands while polling) ----
        float ir = 0.f, iz = 0.f, inn = 0.f;
        if (lane == 0) {
            ir  = gi_ptr[0];
            iz  = gi_ptr[H_DIM];
            inn = gi_ptr[2 * H_DIM];
        }

        if (t > 0) {
            // ---- chip-wide wait for step t's h ----
            if (tid == 0) {
                unsigned target = (unsigned)t << 7;    // t * NCTA
                unsigned v;
                do {
                    asm volatile("ld.acquire.gpu.global.u32 %0, [%1];"
                                 : "=r"(v) : "l"(&g_sync) : "memory");
                } while (v < target);
            }
            __syncthreads();
            // ---- stage h into SMEM: 256 lanes x uint4 = 4KB ----
            if (tid < H_DIM / 8)
                sH[tid] = __ldcg(reinterpret_cast<const uint4*>(&g_h16[t & 1][0]) + tid);
            __syncthreads();
        }

        // ---- matvec: 3 rows, weights in regs, h from SMEM ----
        float acc[3] = {0.f, 0.f, 0.f};
        if (t > 0) {
#pragma unroll
            for (int ii = 0; ii < 4; ii++) {
                uint4 hv0 = sH[(2 * ii) * 32 + lane];
                uint4 hv1 = sH[(2 * ii + 1) * 32 + lane];
                __half2 a0 = u2h2(hv0.x), a1 = u2h2(hv0.y), a2 = u2h2(hv0.z), a3 = u2h2(hv0.w);
                __half2 b0 = u2h2(hv1.x), b1 = u2h2(hv1.y), b2 = u2h2(hv1.z), b3 = u2h2(hv1.w);
#pragma unroll
                for (int g = 0; g < 3; g++) {
                    __half2 s = __hmul2(w[g][2 * ii][0], a0);
                    s = __hfma2(w[g][2 * ii][1], a1, s);
                    s = __hfma2(w[g][2 * ii][2], a2, s);
                    s = __hfma2(w[g][2 * ii][3], a3, s);
                    s = __hfma2(w[g][2 * ii + 1][0], b0, s);
                    s = __hfma2(w[g][2 * ii + 1][1], b1, s);
                    s = __hfma2(w[g][2 * ii + 1][2], b2, s);
                    s = __hfma2(w[g][2 * ii + 1][3], b3, s);
                    float2 f = __half22float2(s);     // flush to fp32 every 16 MACs
                    acc[g] += f.x + f.y;
                }
            }
        }

        // ---- butterfly reduce over 32 lanes ----
#pragma unroll
        for (int off = 16; off; off >>= 1) {
#pragma unroll
            for (int g = 0; g < 3; g++)
                acc[g] += __shfl_xor_sync(0xffffffffu, acc[g], off);
        }

        // ---- gates + state update (lane 0, MUFU fast path) ----
        if (lane == 0) {
            float rg = fsig(ir + bir + acc[0]);
            float zg = fsig(iz + biz + acc[1]);
            float ng = ftanh(inn + bin + rg * (acc[2] + bhn));
            float hn = (1.0f - zg) * ng + zg * h_own;
            h_own = hn;
            out_ptr[0] = hn;
            g_h16[(t + 1) & 1][j] = __float2half(hn);
            if (t == L_SEQ - 1) {
                size_t base = (size_t)L_SEQ * H_DIM;
                if ((long long)(base + j) < out_elems)          out[base + j] = hn;
                if ((long long)(base + H_DIM + j) < out_elems)  out[base + H_DIM + j] = hn;
            }
        }
        __syncthreads();   // all h stores done; also guards sH reuse

        // ---- arrive ----
        if (tid == 0) {
            asm volatile("red.release.gpu.global.add.u32 [%0], %1;"
                         :: "l"(&g_sync), "r"(1u) : "memory");
        }

        gi_ptr  += G3H;
        out_ptr += H_DIM;
    }
}

// ============================================================
extern "C" void kernel_launch(void* const* d_in, const int* in_sizes, int n_in,
                              void* d_out, int out_size) {
    const float* x    = (const float*)d_in[0];
    const float* w_ih = (const float*)d_in[1];
    const float* w_hh = (const float*)d_in[2];
    const float* b_ih = (const float*)d_in[3];
    const float* b_hh = (const float*)d_in[4];
    float* out = (float*)d_out;

    const int nx8 = L_SEQ * H_DIM / 8;       // 524288
    const int nw8 = G3H * H_DIM / 8;         // 1572864
    cvt_x_kernel<<<(nx8 + 255) / 256, 256>>>(x);
    cvt_w_kernel<<<(nw8 + 255) / 256, 256>>>(w_ih);
    gemm_gi_kernel<<<dim3(G3H / GN, L_SEQ / GM), 256>>>();
    gru_kernel<<<NCTA, TPB>>>(w_hh, b_ih, b_hh, out, out_size);
}